// round 8
// baseline (speedup 1.0000x reference)
#include <cuda_runtime.h>
#include <cstdint>

#define BB_   2
#define LL_   2048
#define EE_   1024
#define HH_   16
#define DH_   64
#define FF_   4096
#define NTOK  (BB_*LL_)
#define NZ    (BB_*HH_)

// ---------------- scratch ----------------
__device__ float g_xnh[NTOK*EE_];
__device__ float g_xnl[NTOK*EE_];
__device__ float g_qh [NTOK*EE_];
__device__ float g_ql [NTOK*EE_];
__device__ float g_kh [NTOK*EE_];
__device__ float g_kl [NTOK*EE_];
__device__ float g_v  [NTOK*EE_];
__device__ float g_ctx[NTOK*EE_];
__device__ float g_hidden[NTOK*EE_];
__device__ float g_hn[NTOK*EE_];
__device__ float g_up[(size_t)NTOK*FF_];
__device__ float g_S[(size_t)NZ*LL_*LL_];
// rounded weights
__device__ float g_wqh[EE_*EE_], g_wql[EE_*EE_];
__device__ float g_wkh[EE_*EE_], g_wkl[EE_*EE_];
__device__ float g_wvh[EE_*EE_], g_woh[EE_*EE_];
__device__ float g_wuh[EE_*FF_], g_wdh[FF_*EE_];

// ---------------- helpers ----------------
__device__ __forceinline__ uint32_t f2tf(float x){
    uint32_t r; asm("cvt.rna.tf32.f32 %0, %1;" : "=r"(r) : "f"(x)); return r;
}
__device__ __forceinline__ float rndf(float x){ return __uint_as_float(f2tf(x)); }
__device__ __forceinline__ void mma_tf32(float c[4], const uint32_t a[4], const uint32_t b[2]){
    asm volatile("mma.sync.aligned.m16n8k8.row.col.f32.tf32.tf32.f32 "
        "{%0,%1,%2,%3},{%4,%5,%6,%7},{%8,%9},{%0,%1,%2,%3};"
        : "+f"(c[0]), "+f"(c[1]), "+f"(c[2]), "+f"(c[3])
        : "r"(a[0]), "r"(a[1]), "r"(a[2]), "r"(a[3]), "r"(b[0]), "r"(b[1]));
}
__device__ __forceinline__ void cp16(void* dst, const void* src){
    uint32_t d = (uint32_t)__cvta_generic_to_shared(dst);
    asm volatile("cp.async.cg.shared.global [%0], [%1], 16;" :: "r"(d), "l"(src));
}
__device__ __forceinline__ void cp_commit(){ asm volatile("cp.async.commit_group;" ::: "memory"); }
template<int N> __device__ __forceinline__ void cp_wait(){
    asm volatile("cp.async.wait_group %0;" :: "n"(N) : "memory");
}

// ---------------- weight rounding prep: Hi = rna(W), Lo = rna(W-Hi) ----------------
template<bool LO>
__global__ void roundw_k(const float* __restrict__ W, float* __restrict__ Hi,
                         float* __restrict__ Lo)
{
    const size_t i = ((size_t)blockIdx.x*256 + threadIdx.x)*4;
    float4 v = *(const float4*)(W + i);
    float4 h; h.x = rndf(v.x); h.y = rndf(v.y); h.z = rndf(v.z); h.w = rndf(v.w);
    *(float4*)(Hi + i) = h;
    if (LO){
        float4 l; l.x = rndf(v.x-h.x); l.y = rndf(v.y-h.y);
        l.z = rndf(v.z-h.z); l.w = rndf(v.w-h.w);
        *(float4*)(Lo + i) = l;
    }
}

// ---------------- LayerNorm; outputs tf32-rounded hi (and optionally lo) ----------------
template<bool LO>
__global__ void ln_k(const float* __restrict__ X, const float* __restrict__ w,
                     const float* __restrict__ bb, float* __restrict__ O,
                     float* __restrict__ Olo)
{
    __shared__ float red[256];
    const int t = threadIdx.x;
    const size_t off = (size_t)blockIdx.x * EE_;
    float4 v = *(const float4*)(X + off + t*4);
    red[t] = v.x + v.y + v.z + v.w;
    __syncthreads();
    #pragma unroll
    for (int s = 128; s > 0; s >>= 1){ if (t < s) red[t] += red[t+s]; __syncthreads(); }
    float mu = red[0] * (1.f/1024.f);
    __syncthreads();
    float d0 = v.x-mu, d1 = v.y-mu, d2 = v.z-mu, d3 = v.w-mu;
    red[t] = d0*d0 + d1*d1 + d2*d2 + d3*d3;
    __syncthreads();
    #pragma unroll
    for (int s = 128; s > 0; s >>= 1){ if (t < s) red[t] += red[t+s]; __syncthreads(); }
    float inv = rsqrtf(red[0] * (1.f/1024.f) + 1e-5f);
    float4 wv = *(const float4*)(w + t*4);
    float4 bv = *(const float4*)(bb + t*4);
    float o0 = d0*inv*wv.x + bv.x, o1 = d1*inv*wv.y + bv.y;
    float o2 = d2*inv*wv.z + bv.z, o3 = d3*inv*wv.w + bv.w;
    float4 h; h.x=rndf(o0); h.y=rndf(o1); h.z=rndf(o2); h.w=rndf(o3);
    *(float4*)(O + off + t*4) = h;
    if (LO){
        float4 l; l.x=rndf(o0-h.x); l.y=rndf(o1-h.y); l.z=rndf(o2-h.z); l.w=rndf(o3-h.w);
        *(float4*)(Olo + off + t*4) = l;
    }
}

// ---------------- GEMM: C = epi(A @ W + bias) ----------------
// Inputs pre-rounded to tf32 (hi, and lo when SIN). Inner loop: LDS+MMA only.
// EPI: 0 none(fp32 out) 1 +res(fp32) 2 gelu->round 3 round.  SOUT: write hi/lo.
#define GSS1 8832    // 128*36 + 32*132
#define GSS2 17664

template<int EPI, bool SIN, bool SOUT, int MINB>
__global__ void __launch_bounds__(256, MINB) gemm_k(
    const float* __restrict__ Ah, const float* __restrict__ Al,
    const float* __restrict__ Wh, const float* __restrict__ Wl,
    const float* __restrict__ bias, const float* __restrict__ res,
    float* __restrict__ C, float* __restrict__ Clo, int M, int N, int K)
{
    extern __shared__ float sm[];
    constexpr int STG = SIN ? GSS2 : GSS1;
    const int tid  = threadIdx.x;
    const int bm   = blockIdx.y*128, bn = blockIdx.x*128;
    const int lane = tid & 31, warp = tid >> 5;
    const int wm   = warp >> 2, wn = warp & 3;
    const int gid  = lane >> 2, t4 = lane & 3;

    float acc[4][4][4];
    #pragma unroll
    for (int a=0;a<4;a++)
    #pragma unroll
    for (int b=0;b<4;b++)
    #pragma unroll
    for (int c=0;c<4;c++) acc[a][b][c] = 0.f;

    const int ar = tid >> 3, ac4 = tid & 7;
    const int br = tid >> 5, bc4 = tid & 31;
    const size_t aoff = (size_t)(bm+ar)*K + ac4*4;
    const size_t woff = (size_t)br*N + bn + bc4*4;
    const int KT = K >> 5;

    auto issue = [&](int t){
        float* base = sm + (t&1)*STG;
        const size_t ao = aoff + t*32;
        const size_t wo = woff + (size_t)t*32*N;
        #pragma unroll
        for (int i=0;i<4;i++) cp16(base + (ar+32*i)*36 + ac4*4, Ah + ao + (size_t)(32*i)*K);
        #pragma unroll
        for (int i=0;i<4;i++) cp16(base + 4608 + (br+8*i)*132 + bc4*4, Wh + wo + (size_t)(8*i)*N);
        if (SIN){
            #pragma unroll
            for (int i=0;i<4;i++) cp16(base + GSS1 + (ar+32*i)*36 + ac4*4, Al + ao + (size_t)(32*i)*K);
            #pragma unroll
            for (int i=0;i<4;i++) cp16(base + GSS1 + 4608 + (br+8*i)*132 + bc4*4, Wl + wo + (size_t)(8*i)*N);
        }
        cp_commit();
    };

    issue(0);
    for (int t = 0; t < KT; t++){
        if (t+1 < KT){ issue(t+1); cp_wait<1>(); }
        else         { cp_wait<0>(); }
        __syncthreads();
        const uint32_t* base = (const uint32_t*)(sm + (t&1)*STG);
        const uint32_t* AsH = base;
        const uint32_t* BsH = base + 4608;
        const uint32_t* AsL = base + GSS1;
        const uint32_t* BsL = base + GSS1 + 4608;
        #pragma unroll
        for (int ks=0;ks<4;ks++){
            uint32_t ah[4][4], al[4][4], bh[4][2], bl[4][2];
            #pragma unroll
            for (int mi=0;mi<4;mi++){
                const int r0 = (wm*64 + mi*16 + gid)*36 + ks*8 + t4;
                ah[mi][0]=AsH[r0]; ah[mi][1]=AsH[r0+8*36]; ah[mi][2]=AsH[r0+4]; ah[mi][3]=AsH[r0+8*36+4];
                if (SIN){
                    al[mi][0]=AsL[r0]; al[mi][1]=AsL[r0+8*36]; al[mi][2]=AsL[r0+4]; al[mi][3]=AsL[r0+8*36+4];
                }
            }
            #pragma unroll
            for (int ni=0;ni<4;ni++){
                const int c0 = wn*32 + ni*8 + gid;
                bh[ni][0]=BsH[(ks*8+t4)*132 + c0]; bh[ni][1]=BsH[(ks*8+t4+4)*132 + c0];
                if (SIN){
                    bl[ni][0]=BsL[(ks*8+t4)*132 + c0]; bl[ni][1]=BsL[(ks*8+t4+4)*132 + c0];
                }
            }
            #pragma unroll
            for (int mi=0;mi<4;mi++)
            #pragma unroll
            for (int ni=0;ni<4;ni++){
                mma_tf32(acc[mi][ni], ah[mi], bh[ni]);
                if (SIN){
                    mma_tf32(acc[mi][ni], ah[mi], bl[ni]);
                    mma_tf32(acc[mi][ni], al[mi], bh[ni]);
                }
            }
        }
        __syncthreads();
    }

    #pragma unroll
    for (int mi=0;mi<4;mi++)
    #pragma unroll
    for (int ni=0;ni<4;ni++){
        const int row0 = bm + wm*64 + mi*16 + gid;
        const int col0 = bn + wn*32 + ni*8 + t4*2;
        #pragma unroll
        for (int i=0;i<4;i++){
            const int row = row0 + ((i>=2)?8:0);
            const int col = col0 + (i&1);
            float v = acc[mi][ni][i] + bias[col];
            const size_t o = (size_t)row*N + col;
            if (SOUT){
                float h = rndf(v);
                C[o] = h; Clo[o] = rndf(v - h);
            } else if (EPI == 1){
                C[o] = v + res[o];
            } else if (EPI == 2){
                v = 0.5f*v*(1.0f + erff(v*0.70710678118654752f));
                C[o] = rndf(v);
            } else if (EPI == 3){
                C[o] = rndf(v);
            } else {
                C[o] = v;
            }
        }
    }
}

// ---------------- scores: S[z,l,m] = 8 * q.k  (pre-split hi/lo operands) ----------------
__global__ void __launch_bounds__(256) attn_score_k(
    const float* __restrict__ Qh, const float* __restrict__ Ql,
    const float* __restrict__ Kh, const float* __restrict__ Kl,
    float* __restrict__ S)
{
    extern __shared__ float sm[];
    float* QsH = sm; float* QsL = sm + 4608; float* KsH = sm + 9216; float* KsL = sm + 13824;
    const int tid  = threadIdx.x;
    const int z = blockIdx.z, b = z >> 4, h = z & 15;
    const int bm = blockIdx.y*128, bn = blockIdx.x*128;
    const int lane = tid & 31, warp = tid >> 5;
    const int wm = warp >> 2, wn = warp & 3;
    const int gid = lane >> 2, t4 = lane & 3;

    float acc[4][4][4];
    #pragma unroll
    for (int a=0;a<4;a++)
    #pragma unroll
    for (int c=0;c<4;c++)
    #pragma unroll
    for (int i=0;i<4;i++) acc[a][c][i] = 0.f;

    const int ar = tid >> 3, ac4 = tid & 7;
    const size_t qo = ((size_t)(b*LL_ + bm + ar)*HH_ + h)*DH_ + ac4*4;
    const size_t ko = ((size_t)(b*LL_ + bn + ar)*HH_ + h)*DH_ + ac4*4;

    #pragma unroll
    for (int kt = 0; kt < 2; kt++){
        float4 r0[4], r1[4], r2[4], r3[4];
        #pragma unroll
        for (int i=0;i<4;i++){
            const size_t so = kt*32 + (size_t)(32*i)*1024;
            r0[i] = *(const float4*)(Qh + qo + so);
            r1[i] = *(const float4*)(Ql + qo + so);
            r2[i] = *(const float4*)(Kh + ko + so);
            r3[i] = *(const float4*)(Kl + ko + so);
        }
        if (kt) __syncthreads();
        #pragma unroll
        for (int i=0;i<4;i++){
            const int so = (ar+32*i)*36 + ac4*4;
            *(float4*)(QsH + so) = r0[i];
            *(float4*)(QsL + so) = r1[i];
            *(float4*)(KsH + so) = r2[i];
            *(float4*)(KsL + so) = r3[i];
        }
        __syncthreads();
        const uint32_t* qh = (const uint32_t*)QsH; const uint32_t* ql = (const uint32_t*)QsL;
        const uint32_t* kh = (const uint32_t*)KsH; const uint32_t* kl = (const uint32_t*)KsL;
        #pragma unroll
        for (int ks=0;ks<4;ks++){
            uint32_t ah[4][4], al[4][4], bh[4][2], bl[4][2];
            #pragma unroll
            for (int mi=0;mi<4;mi++){
                const int r = (wm*64 + mi*16 + gid)*36 + ks*8 + t4;
                ah[mi][0]=qh[r]; ah[mi][1]=qh[r+8*36]; ah[mi][2]=qh[r+4]; ah[mi][3]=qh[r+8*36+4];
                al[mi][0]=ql[r]; al[mi][1]=ql[r+8*36]; al[mi][2]=ql[r+4]; al[mi][3]=ql[r+8*36+4];
            }
            #pragma unroll
            for (int ni=0;ni<4;ni++){
                const int c0 = wn*32 + ni*8 + gid;
                bh[ni][0]=kh[c0*36 + ks*8 + t4]; bh[ni][1]=kh[c0*36 + ks*8 + t4 + 4];
                bl[ni][0]=kl[c0*36 + ks*8 + t4]; bl[ni][1]=kl[c0*36 + ks*8 + t4 + 4];
            }
            #pragma unroll
            for (int mi=0;mi<4;mi++)
            #pragma unroll
            for (int ni=0;ni<4;ni++){
                mma_tf32(acc[mi][ni], ah[mi], bh[ni]);
                mma_tf32(acc[mi][ni], ah[mi], bl[ni]);
                mma_tf32(acc[mi][ni], al[mi], bh[ni]);
            }
        }
    }

    float* Sz = S + (size_t)z*LL_*LL_;
    #pragma unroll
    for (int mi=0;mi<4;mi++)
    #pragma unroll
    for (int ni=0;ni<4;ni++){
        const int row0 = bm + wm*64 + mi*16 + gid;
        const int col0 = bn + wn*32 + ni*8 + t4*2;
        #pragma unroll
        for (int i=0;i<4;i++){
            const int row = row0 + ((i>=2)?8:0);
            const int col = col0 + (i&1);
            Sz[(size_t)row*LL_ + col] = 8.0f * acc[mi][ni][i];
        }
    }
}

// ---------------- row softmax (2048), rounds output to tf32 ----------------
__global__ void softmax_k(float* __restrict__ S)
{
    __shared__ float red[256];
    const int t = threadIdx.x;
    float4* row = (float4*)(S + (size_t)blockIdx.y*LL_*LL_ + (size_t)blockIdx.x*LL_);
    float4 v0 = row[t], v1 = row[t+256];
    float m = fmaxf(fmaxf(fmaxf(v0.x,v0.y), fmaxf(v0.z,v0.w)),
                    fmaxf(fmaxf(v1.x,v1.y), fmaxf(v1.z,v1.w)));
    red[t] = m; __syncthreads();
    #pragma unroll
    for (int s=128;s>0;s>>=1){ if (t<s) red[t] = fmaxf(red[t], red[t+s]); __syncthreads(); }
    m = red[0]; __syncthreads();
    v0.x = expf(v0.x-m); v0.y = expf(v0.y-m); v0.z = expf(v0.z-m); v0.w = expf(v0.w-m);
    v1.x = expf(v1.x-m); v1.y = expf(v1.y-m); v1.z = expf(v1.z-m); v1.w = expf(v1.w-m);
    red[t] = v0.x+v0.y+v0.z+v0.w + v1.x+v1.y+v1.z+v1.w;
    __syncthreads();
    #pragma unroll
    for (int s=128;s>0;s>>=1){ if (t<s) red[t] += red[t+s]; __syncthreads(); }
    const float inv = 1.0f / red[0];
    v0.x=rndf(v0.x*inv); v0.y=rndf(v0.y*inv); v0.z=rndf(v0.z*inv); v0.w=rndf(v0.w*inv);
    v1.x=rndf(v1.x*inv); v1.y=rndf(v1.y*inv); v1.z=rndf(v1.z*inv); v1.w=rndf(v1.w*inv);
    row[t] = v0; row[t+256] = v1;
}

// ---------------- ctx = P @ V (operands pre-rounded); ctx rounded for O-gemm ----------------
#define VSS 6912

__global__ void __launch_bounds__(256, 2) attn_av_k(
    const float* __restrict__ P, const float* __restrict__ V, float* __restrict__ Ctx)
{
    extern __shared__ float sm[];
    const int tid  = threadIdx.x;
    const int z = blockIdx.y, b = z >> 4, h = z & 15;
    const int bm = blockIdx.x*128;
    const int lane = tid & 31, warp = tid >> 5;
    const int wm = warp >> 1, wn = warp & 1;
    const int gid = lane >> 2, t4 = lane & 3;

    float acc[2][4][4];
    #pragma unroll
    for (int a=0;a<2;a++)
    #pragma unroll
    for (int c=0;c<4;c++)
    #pragma unroll
    for (int i=0;i<4;i++) acc[a][c][i] = 0.f;

    const int ar = tid >> 3, ac4 = tid & 7;
    const int vr = tid >> 4, vc4 = tid & 15;
    const float* Pp = P + (size_t)z*LL_*LL_ + (size_t)(bm+ar)*LL_ + ac4*4;
    const float* Vp = V + ((size_t)(b*LL_ + vr)*HH_ + h)*DH_ + vc4*4;
    const int KT = LL_/32;

    auto issue = [&](int t){
        float* Ps = sm + (t&1)*VSS;
        float* Vs = Ps + 4608;
        const int k0 = t*32;
        #pragma unroll
        for (int i=0;i<4;i++) cp16(Ps + (ar+32*i)*36 + ac4*4, Pp + k0 + (size_t)(32*i)*LL_);
        #pragma unroll
        for (int i=0;i<2;i++) cp16(Vs + (vr+16*i)*72 + vc4*4, Vp + (size_t)(k0+16*i)*1024);
        cp_commit();
    };

    issue(0);
    for (int t = 0; t < KT; t++){
        if (t+1 < KT){ issue(t+1); cp_wait<1>(); }
        else         { cp_wait<0>(); }
        __syncthreads();
        const uint32_t* Ps = (const uint32_t*)(sm + (t&1)*VSS);
        const uint32_t* Vs = Ps + 4608;
        #pragma unroll
        for (int ks=0;ks<4;ks++){
            uint32_t a[2][4], bfr[4][2];
            #pragma unroll
            for (int mi=0;mi<2;mi++){
                const int r0 = (wm*32 + mi*16 + gid)*36 + ks*8 + t4;
                a[mi][0]=Ps[r0]; a[mi][1]=Ps[r0+8*36]; a[mi][2]=Ps[r0+4]; a[mi][3]=Ps[r0+8*36+4];
            }
            #pragma unroll
            for (int ni=0;ni<4;ni++){
                const int c0 = wn*32 + ni*8 + gid;
                bfr[ni][0] = Vs[(ks*8+t4)*72 + c0];
                bfr[ni][1] = Vs[(ks*8+t4+4)*72 + c0];
            }
            #pragma unroll
            for (int mi=0;mi<2;mi++)
            #pragma unroll
            for (int ni=0;ni<4;ni++)
                mma_tf32(acc[mi][ni], a[mi], bfr[ni]);
        }
        __syncthreads();
    }

    #pragma unroll
    for (int mi=0;mi<2;mi++)
    #pragma unroll
    for (int ni=0;ni<4;ni++){
        const int row0 = bm + wm*32 + mi*16 + gid;
        const int col0 = wn*32 + ni*8 + t4*2;
        #pragma unroll
        for (int i=0;i<4;i++){
            const int row = row0 + ((i>=2)?8:0);
            const int col = col0 + (i&1);
            Ctx[((size_t)(b*LL_ + row)*HH_ + h)*DH_ + col] = rndf(acc[mi][ni][i]);
        }
    }
}

// ---------------- launch ----------------
extern "C" void kernel_launch(void* const* d_in, const int* in_sizes, int n_in,
                              void* d_out, int out_size)
{
    const float* x     = (const float*)d_in[0];
    const float* ln1_w = (const float*)d_in[1];
    const float* ln1_b = (const float*)d_in[2];
    const float* wq    = (const float*)d_in[3];
    const float* bq    = (const float*)d_in[4];
    const float* wk    = (const float*)d_in[5];
    const float* bk    = (const float*)d_in[6];
    const float* wv    = (const float*)d_in[7];
    const float* bv    = (const float*)d_in[8];
    const float* wo    = (const float*)d_in[9];
    const float* bo    = (const float*)d_in[10];
    const float* ln2_w = (const float*)d_in[11];
    const float* ln2_b = (const float*)d_in[12];
    const float* wu    = (const float*)d_in[13];
    const float* bu    = (const float*)d_in[14];
    const float* wd    = (const float*)d_in[15];
    const float* bd    = (const float*)d_in[16];
    float* out = (float*)d_out;

    float *xnh,*xnl,*qh,*ql,*kh,*kl,*v,*ctx,*hidden,*hn,*up,*S;
    float *wqh,*wql,*wkh,*wkl,*wvh,*woh,*wuh,*wdh;
    cudaGetSymbolAddress((void**)&xnh, g_xnh);  cudaGetSymbolAddress((void**)&xnl, g_xnl);
    cudaGetSymbolAddress((void**)&qh,  g_qh);   cudaGetSymbolAddress((void**)&ql,  g_ql);
    cudaGetSymbolAddress((void**)&kh,  g_kh);   cudaGetSymbolAddress((void**)&kl,  g_kl);
    cudaGetSymbolAddress((void**)&v,   g_v);    cudaGetSymbolAddress((void**)&ctx, g_ctx);
    cudaGetSymbolAddress((void**)&hidden, g_hidden);
    cudaGetSymbolAddress((void**)&hn,  g_hn);   cudaGetSymbolAddress((void**)&up,  g_up);
    cudaGetSymbolAddress((void**)&S,   g_S);
    cudaGetSymbolAddress((void**)&wqh, g_wqh);  cudaGetSymbolAddress((void**)&wql, g_wql);
    cudaGetSymbolAddress((void**)&wkh, g_wkh);  cudaGetSymbolAddress((void**)&wkl, g_wkl);
    cudaGetSymbolAddress((void**)&wvh, g_wvh);  cudaGetSymbolAddress((void**)&woh, g_woh);
    cudaGetSymbolAddress((void**)&wuh, g_wuh);  cudaGetSymbolAddress((void**)&wdh, g_wdh);

    const int SM1 = 2*GSS1*4;    // 70656
    const int SM2 = 2*GSS2*4;    // 141312
    const int SMS = 4*4608*4;    // 73728 (score)
    const int SMV = 2*VSS*4;     // 55296
    cudaFuncSetAttribute(gemm_k<0,true ,true ,1>, cudaFuncAttributeMaxDynamicSharedMemorySize, SM2);
    cudaFuncSetAttribute(gemm_k<3,false,false,2>, cudaFuncAttributeMaxDynamicSharedMemorySize, SM1);
    cudaFuncSetAttribute(gemm_k<1,false,false,2>, cudaFuncAttributeMaxDynamicSharedMemorySize, SM1);
    cudaFuncSetAttribute(gemm_k<2,false,false,2>, cudaFuncAttributeMaxDynamicSharedMemorySize, SM1);
    cudaFuncSetAttribute(attn_score_k,            cudaFuncAttributeMaxDynamicSharedMemorySize, SMS);
    cudaFuncSetAttribute(attn_av_k,               cudaFuncAttributeMaxDynamicSharedMemorySize, SMV);

    const dim3 blk(256);
    const dim3 gE(EE_/128, NTOK/128);
    const dim3 gF(FF_/128, NTOK/128);

    // 0. weight rounding prep
    roundw_k<true ><<<EE_*EE_/1024, blk>>>(wq, wqh, wql);
    roundw_k<true ><<<EE_*EE_/1024, blk>>>(wk, wkh, wkl);
    roundw_k<false><<<EE_*EE_/1024, blk>>>(wv, wvh, nullptr);
    roundw_k<false><<<EE_*EE_/1024, blk>>>(wo, woh, nullptr);
    roundw_k<false><<<EE_*FF_/1024, blk>>>(wu, wuh, nullptr);
    roundw_k<false><<<FF_*EE_/1024, blk>>>(wd, wdh, nullptr);
    // 1. LN1 (hi+lo)
    ln_k<true><<<NTOK, blk>>>(x, ln1_w, ln1_b, xnh, xnl);
    // 2. Q, K (split in+out), V (round out)
    gemm_k<0,true ,true ,1><<<gE, blk, SM2>>>(xnh, xnl, wqh, wql, bq, nullptr, qh, ql, NTOK, EE_, EE_);
    gemm_k<0,true ,true ,1><<<gE, blk, SM2>>>(xnh, xnl, wkh, wkl, bk, nullptr, kh, kl, NTOK, EE_, EE_);
    gemm_k<3,false,false,2><<<gE, blk, SM1>>>(xnh, nullptr, wvh, nullptr, bv, nullptr, v, nullptr, NTOK, EE_, EE_);
    // 3. scores, softmax (rounds P), context (rounds ctx)
    attn_score_k<<<dim3(LL_/128, LL_/128, NZ), blk, SMS>>>(qh, ql, kh, kl, S);
    softmax_k   <<<dim3(LL_, NZ), blk>>>(S);
    attn_av_k   <<<dim3(LL_/128, NZ), blk, SMV>>>(S, v, ctx);
    // 4. O proj + residual (fp32 out)
    gemm_k<1,false,false,2><<<gE, blk, SM1>>>(ctx, nullptr, woh, nullptr, bo, x, hidden, nullptr, NTOK, EE_, EE_);
    // 5. LN2 (hi only) + FFN
    ln_k<false><<<NTOK, blk>>>(hidden, ln2_w, ln2_b, hn, nullptr);
    gemm_k<2,false,false,2><<<gF, blk, SM1>>>(hn, nullptr, wuh, nullptr, bu, nullptr, up, nullptr, NTOK, FF_, EE_);
    gemm_k<1,false,false,2><<<gE, blk, SM1>>>(up, nullptr, wdh, nullptr, bd, hidden, out, nullptr, NTOK, EE_, FF_);
    (void)in_sizes; (void)n_in; (void)out_size;
}